// round 1
// baseline (speedup 1.0000x reference)
#include <cuda_runtime.h>
#include <cstdint>

#define FULL 0xFFFFFFFFu

static constexpr int NTOK = 49;      // tokens per window
static constexpr int S_STR = 260;    // smem row stride (floats); 260 % 32 == 4 -> conflict-free frags
static constexpr int SM_Q = 0;
static constexpr int SM_K = NTOK * S_STR;
static constexpr int SM_V = 2 * NTOK * S_STR;
static constexpr int SM_X = 3 * NTOK * S_STR;          // union: x tile (phase1) / attn out (phase2+)
static constexpr int SMEM_FLOATS = 4 * NTOK * S_STR;   // 50960 floats = 203840 B

// tf32-rounded copies of the weight matrices (rounded once per launch, reused by all 4096 CTAs)
__device__ float g_wqkv[256 * 768];
__device__ float g_wproj[256 * 256];

__device__ __forceinline__ unsigned f2tf(float x) {
    unsigned r;
    asm("cvt.rna.tf32.f32 %0, %1;" : "=r"(r) : "f"(x));
    return r;
}
__device__ __forceinline__ float tfr(float x) { return __uint_as_float(f2tf(x)); }

// D += A(16x8,tf32) * B(8x8,tf32)   (m16n8k8, row.col, f32 accum)
__device__ __forceinline__ void mma8(float d[4], const unsigned a[4], const unsigned b[2]) {
    asm volatile(
        "mma.sync.aligned.m16n8k8.row.col.f32.tf32.tf32.f32 "
        "{%0,%1,%2,%3}, {%4,%5,%6,%7}, {%8,%9}, {%0,%1,%2,%3};\n"
        : "+f"(d[0]), "+f"(d[1]), "+f"(d[2]), "+f"(d[3])
        : "r"(a[0]), "r"(a[1]), "r"(a[2]), "r"(a[3]), "r"(b[0]), "r"(b[1]));
}

__global__ void prep_weights(const float* __restrict__ wqkv, const float* __restrict__ wproj) {
    int i = blockIdx.x * blockDim.x + threadIdx.x;
    if (i < 256 * 768) g_wqkv[i] = tfr(wqkv[i]);
    if (i < 256 * 256) g_wproj[i] = tfr(wproj[i]);
}

__global__ void __launch_bounds__(256, 1)
winattn_kernel(const float* __restrict__ x,
               const float* __restrict__ b_qkv,
               const float* __restrict__ b_proj,
               const float* __restrict__ bias_table,
               float* __restrict__ out)
{
    extern __shared__ float sm[];
    float* sq = sm + SM_Q;
    float* sk = sm + SM_K;
    float* sv = sm + SM_V;
    float* sx = sm + SM_X;   // phase1: x tile; phase2+: attention output (proj A operand)

    const int tid  = threadIdx.x;
    const int warp = tid >> 5;
    const int lane = tid & 31;
    const int g    = lane >> 2;   // groupID (row within frag)
    const int tg   = lane & 3;    // thread-in-group (col within frag)
    const int b    = blockIdx.x;

    // ---- load x[b] (49x256) into smem, rounded to tf32 ----
    const float* xb = x + (size_t)b * NTOK * 256;
    for (int i = tid; i < NTOK * 256 / 4; i += 256) {
        float4 v = ((const float4*)xb)[i];
        int e = i * 4;
        int r = e >> 8, c = e & 255;
        float* d = sx + r * S_STR + c;
        d[0] = tfr(v.x); d[1] = tfr(v.y); d[2] = tfr(v.z); d[3] = tfr(v.w);
    }
    __syncthreads();

    const int wm = warp >> 2;  // 0..1 : row-half of the 64-row tile
    const int wn = warp & 3;   // 0..3 : 32-col slice within a 128-col chunk

    // ================= GEMM1: qkv = x @ w_qkv + b_qkv =================
    for (int nc = 0; nc < 6; nc++) {
        const int nb = nc * 128 + wn * 32;
        float acc[2][4][4];
        #pragma unroll
        for (int mt = 0; mt < 2; mt++)
            #pragma unroll
            for (int nt = 0; nt < 4; nt++)
                #pragma unroll
                for (int q = 0; q < 4; q++) acc[mt][nt][q] = 0.f;

        #pragma unroll 2
        for (int ks = 0; ks < 32; ks++) {
            const int k0 = ks * 8;
            unsigned A[2][4];
            #pragma unroll
            for (int mt = 0; mt < 2; mt++) {
                int r = wm * 32 + mt * 16 + g;
                A[mt][0] = (r     < NTOK) ? __float_as_uint(sx[r       * S_STR + k0 + tg    ]) : 0u;
                A[mt][1] = (r + 8 < NTOK) ? __float_as_uint(sx[(r + 8) * S_STR + k0 + tg    ]) : 0u;
                A[mt][2] = (r     < NTOK) ? __float_as_uint(sx[r       * S_STR + k0 + tg + 4]) : 0u;
                A[mt][3] = (r + 8 < NTOK) ? __float_as_uint(sx[(r + 8) * S_STR + k0 + tg + 4]) : 0u;
            }
            #pragma unroll
            for (int nt = 0; nt < 4; nt++) {
                int n0 = nb + nt * 8 + g;
                unsigned Bf[2];
                Bf[0] = __float_as_uint(g_wqkv[(k0 + tg    ) * 768 + n0]);
                Bf[1] = __float_as_uint(g_wqkv[(k0 + tg + 4) * 768 + n0]);
                mma8(acc[0][nt], A[0], Bf);
                mma8(acc[1][nt], A[1], Bf);
            }
        }
        // epilogue: +bias, round to tf32, scatter into sq/sk/sv
        #pragma unroll
        for (int mt = 0; mt < 2; mt++) {
            int r = wm * 32 + mt * 16 + g;
            #pragma unroll
            for (int nt = 0; nt < 4; nt++) {
                int c   = nb + nt * 8 + 2 * tg;
                int sel = c >> 8;
                int cc  = c & 255;
                float* dst = (sel == 0) ? sq : (sel == 1) ? sk : sv;
                float bq0 = b_qkv[c], bq1 = b_qkv[c + 1];
                if (r < NTOK) {
                    float2 v; v.x = tfr(acc[mt][nt][0] + bq0); v.y = tfr(acc[mt][nt][1] + bq1);
                    *(float2*)(dst + r * S_STR + cc) = v;
                }
                if (r + 8 < NTOK) {
                    float2 v; v.x = tfr(acc[mt][nt][2] + bq0); v.y = tfr(acc[mt][nt][3] + bq1);
                    *(float2*)(dst + (r + 8) * S_STR + cc) = v;
                }
            }
        }
    }
    __syncthreads();

    // ================= Attention: one head per warp =================
    const int   h     = warp;
    const float scale = 0.17677669529663687f;   // 1/sqrt(32)
    float* sout = sx;                           // reuse x region for attention output

    for (int m0 = 0; m0 < 64; m0 += 16) {
        float S[7][4];
        #pragma unroll
        for (int jt = 0; jt < 7; jt++)
            #pragma unroll
            for (int q = 0; q < 4; q++) S[jt][q] = 0.f;

        // S = q @ k^T   (M=16 rows m0.., N=56 (49 valid), K=32)
        #pragma unroll
        for (int kt = 0; kt < 4; kt++) {
            int c0 = h * 32 + kt * 8 + tg;
            int r  = m0 + g;
            unsigned A[4];
            A[0] = (r     < NTOK) ? __float_as_uint(sq[r       * S_STR + c0    ]) : 0u;
            A[1] = (r + 8 < NTOK) ? __float_as_uint(sq[(r + 8) * S_STR + c0    ]) : 0u;
            A[2] = (r     < NTOK) ? __float_as_uint(sq[r       * S_STR + c0 + 4]) : 0u;
            A[3] = (r + 8 < NTOK) ? __float_as_uint(sq[(r + 8) * S_STR + c0 + 4]) : 0u;
            #pragma unroll
            for (int jt = 0; jt < 7; jt++) {
                int tok = jt * 8 + g;
                unsigned Bf[2];
                Bf[0] = (tok < NTOK) ? __float_as_uint(sk[tok * S_STR + c0    ]) : 0u;
                Bf[1] = (tok < NTOK) ? __float_as_uint(sk[tok * S_STR + c0 + 4]) : 0u;
                mma8(S[jt], A, Bf);
            }
        }

        // scale + relative-position bias + mask
        int r0 = m0 + g, r1 = m0 + 8 + g;
        int r0c = (r0 < NTOK) ? r0 : 0;
        int r1c = (r1 < NTOK) ? r1 : 0;
        int hi0 = r0c / 7, wi0 = r0c % 7;
        int hi1 = r1c / 7, wi1 = r1c % 7;
        #pragma unroll
        for (int jt = 0; jt < 7; jt++) {
            #pragma unroll
            for (int e = 0; e < 2; e++) {
                int j = jt * 8 + 2 * tg + e;
                if (j < NTOK) {
                    int hj = j / 7, wj = j % 7;
                    float b0v = bias_table[((hi0 - hj + 6) * 13 + (wi0 - wj + 6)) * 8 + h];
                    float b1v = bias_table[((hi1 - hj + 6) * 13 + (wi1 - wj + 6)) * 8 + h];
                    S[jt][e]     = S[jt][e]     * scale + b0v;
                    S[jt][2 + e] = S[jt][2 + e] * scale + b1v;
                } else {
                    S[jt][e]     = -1e30f;
                    S[jt][2 + e] = -1e30f;
                }
            }
        }

        // softmax (row r0 lives in regs 0/1, row r1 in regs 2/3; quad reduction over tg)
        float mx0 = -1e30f, mx1 = -1e30f;
        #pragma unroll
        for (int jt = 0; jt < 7; jt++) {
            mx0 = fmaxf(mx0, fmaxf(S[jt][0], S[jt][1]));
            mx1 = fmaxf(mx1, fmaxf(S[jt][2], S[jt][3]));
        }
        mx0 = fmaxf(mx0, __shfl_xor_sync(FULL, mx0, 1));
        mx0 = fmaxf(mx0, __shfl_xor_sync(FULL, mx0, 2));
        mx1 = fmaxf(mx1, __shfl_xor_sync(FULL, mx1, 1));
        mx1 = fmaxf(mx1, __shfl_xor_sync(FULL, mx1, 2));
        float s0 = 0.f, s1 = 0.f;
        #pragma unroll
        for (int jt = 0; jt < 7; jt++) {
            S[jt][0] = __expf(S[jt][0] - mx0); s0 += S[jt][0];
            S[jt][1] = __expf(S[jt][1] - mx0); s0 += S[jt][1];
            S[jt][2] = __expf(S[jt][2] - mx1); s1 += S[jt][2];
            S[jt][3] = __expf(S[jt][3] - mx1); s1 += S[jt][3];
        }
        s0 += __shfl_xor_sync(FULL, s0, 1); s0 += __shfl_xor_sync(FULL, s0, 2);
        s1 += __shfl_xor_sync(FULL, s1, 1); s1 += __shfl_xor_sync(FULL, s1, 2);
        float i0 = 1.f / s0, i1 = 1.f / s1;

        unsigned Pt[7][4];
        #pragma unroll
        for (int jt = 0; jt < 7; jt++) {
            Pt[jt][0] = f2tf(S[jt][0] * i0);
            Pt[jt][1] = f2tf(S[jt][1] * i0);
            Pt[jt][2] = f2tf(S[jt][2] * i1);
            Pt[jt][3] = f2tf(S[jt][3] * i1);
        }

        // O = P @ v   (C-frag -> A-frag permute via intra-quad shfl)
        float O[4][4];
        #pragma unroll
        for (int nt = 0; nt < 4; nt++)
            #pragma unroll
            for (int q = 0; q < 4; q++) O[nt][q] = 0.f;

        const int  src = g * 4 + (tg >> 1);
        const bool odd = (tg & 1);
        #pragma unroll
        for (int kt = 0; kt < 7; kt++) {
            unsigned q0 = __shfl_sync(FULL, Pt[kt][0], src);
            unsigned q1 = __shfl_sync(FULL, Pt[kt][1], src);
            unsigned q2 = __shfl_sync(FULL, Pt[kt][2], src);
            unsigned q3 = __shfl_sync(FULL, Pt[kt][3], src);
            unsigned q4 = __shfl_sync(FULL, Pt[kt][0], src + 2);
            unsigned q5 = __shfl_sync(FULL, Pt[kt][1], src + 2);
            unsigned q6 = __shfl_sync(FULL, Pt[kt][2], src + 2);
            unsigned q7 = __shfl_sync(FULL, Pt[kt][3], src + 2);
            unsigned A[4];
            A[0] = odd ? q1 : q0;   // P[g    ][8kt+tg  ]
            A[1] = odd ? q3 : q2;   // P[g+8  ][8kt+tg  ]
            A[2] = odd ? q5 : q4;   // P[g    ][8kt+tg+4]
            A[3] = odd ? q7 : q6;   // P[g+8  ][8kt+tg+4]
            #pragma unroll
            for (int nt = 0; nt < 4; nt++) {
                int col = h * 32 + nt * 8 + g;
                int t0  = kt * 8 + tg;
                unsigned Bf[2];
                Bf[0] = (t0     < NTOK) ? __float_as_uint(sv[t0       * S_STR + col]) : 0u;
                Bf[1] = (t0 + 4 < NTOK) ? __float_as_uint(sv[(t0 + 4) * S_STR + col]) : 0u;
                mma8(O[nt], A, Bf);
            }
        }
        #pragma unroll
        for (int nt = 0; nt < 4; nt++) {
            int c = h * 32 + nt * 8 + 2 * tg;
            if (r0 < NTOK) {
                float2 v; v.x = tfr(O[nt][0]); v.y = tfr(O[nt][1]);
                *(float2*)(sout + r0 * S_STR + c) = v;
            }
            if (r1 < NTOK) {
                float2 v; v.x = tfr(O[nt][2]); v.y = tfr(O[nt][3]);
                *(float2*)(sout + r1 * S_STR + c) = v;
            }
        }
    }
    __syncthreads();

    // ================= Proj: out = attn_out @ w_proj + b_proj =================
    for (int pc = 0; pc < 2; pc++) {
        const int nb = pc * 128 + wn * 32;
        float acc[2][4][4];
        #pragma unroll
        for (int mt = 0; mt < 2; mt++)
            #pragma unroll
            for (int nt = 0; nt < 4; nt++)
                #pragma unroll
                for (int q = 0; q < 4; q++) acc[mt][nt][q] = 0.f;

        #pragma unroll 2
        for (int ks = 0; ks < 32; ks++) {
            const int k0 = ks * 8;
            unsigned A[2][4];
            #pragma unroll
            for (int mt = 0; mt < 2; mt++) {
                int r = wm * 32 + mt * 16 + g;
                A[mt][0] = (r     < NTOK) ? __float_as_uint(sout[r       * S_STR + k0 + tg    ]) : 0u;
                A[mt][1] = (r + 8 < NTOK) ? __float_as_uint(sout[(r + 8) * S_STR + k0 + tg    ]) : 0u;
                A[mt][2] = (r     < NTOK) ? __float_as_uint(sout[r       * S_STR + k0 + tg + 4]) : 0u;
                A[mt][3] = (r + 8 < NTOK) ? __float_as_uint(sout[(r + 8) * S_STR + k0 + tg + 4]) : 0u;
            }
            #pragma unroll
            for (int nt = 0; nt < 4; nt++) {
                int n0 = nb + nt * 8 + g;
                unsigned Bf[2];
                Bf[0] = __float_as_uint(g_wproj[(k0 + tg    ) * 256 + n0]);
                Bf[1] = __float_as_uint(g_wproj[(k0 + tg + 4) * 256 + n0]);
                mma8(acc[0][nt], A[0], Bf);
                mma8(acc[1][nt], A[1], Bf);
            }
        }
        #pragma unroll
        for (int mt = 0; mt < 2; mt++) {
            int r = wm * 32 + mt * 16 + g;
            #pragma unroll
            for (int nt = 0; nt < 4; nt++) {
                int c = nb + nt * 8 + 2 * tg;
                float bp0 = b_proj[c], bp1 = b_proj[c + 1];
                if (r < NTOK) {
                    float2 v; v.x = acc[mt][nt][0] + bp0; v.y = acc[mt][nt][1] + bp1;
                    *(float2*)(out + ((size_t)b * NTOK + r) * 256 + c) = v;
                }
                if (r + 8 < NTOK) {
                    float2 v; v.x = acc[mt][nt][2] + bp0; v.y = acc[mt][nt][3] + bp1;
                    *(float2*)(out + ((size_t)b * NTOK + r + 8) * 256 + c) = v;
                }
            }
        }
    }
}

extern "C" void kernel_launch(void* const* d_in, const int* in_sizes, int n_in,
                              void* d_out, int out_size)
{
    const float* x          = (const float*)d_in[0];
    const float* w_qkv      = (const float*)d_in[1];
    const float* b_qkv      = (const float*)d_in[2];
    const float* w_proj     = (const float*)d_in[3];
    const float* b_proj     = (const float*)d_in[4];
    const float* bias_table = (const float*)d_in[5];

    const int B = in_sizes[0] / (NTOK * 256);

    cudaFuncSetAttribute(winattn_kernel,
                         cudaFuncAttributeMaxDynamicSharedMemorySize,
                         SMEM_FLOATS * (int)sizeof(float));

    prep_weights<<<768, 256>>>(w_qkv, w_proj);
    winattn_kernel<<<B, 256, SMEM_FLOATS * sizeof(float)>>>(
        x, b_qkv, b_proj, bias_table, (float*)d_out);
}

// round 2
// speedup vs baseline: 1.1023x; 1.1023x over previous
#include <cuda_runtime.h>
#include <cstdint>

#define FULL 0xFFFFFFFFu

static constexpr int NTOK = 49;      // tokens per window
static constexpr int S_STR = 260;    // smem row stride; 260 % 32 == 4 -> conflict-free fragments
// region layout (floats). Over-reads of "padded" A rows 49..63 intentionally spill into the
// next region; those mma output rows are discarded by store predicates.
static constexpr int SM_X = 0;                    // 49 rows: x tile, later attention output
static constexpr int SM_Q = 49 * S_STR;           // 49 rows
static constexpr int SM_K = SM_Q + 49 * S_STR;    // 56 rows (rows 49..55 read by B-frags, masked)
static constexpr int SM_V = SM_K + 56 * S_STR;    // 56 rows (rows 49..55 MUST be zero: 0*Inf=NaN)
static constexpr int SM_B = SM_V + 56 * S_STR;    // bias table 169*8 floats
static constexpr int SMEM_FLOATS = SM_B + 169 * 8;   // 55952 floats = 223808 B

// tf32-rounded weights (rounded once per launch, reused by all CTAs)
__device__ float g_wqkv[256 * 768];
__device__ float g_wproj[256 * 256];

__device__ __forceinline__ unsigned f2tf(float x) {
    unsigned r;
    asm("cvt.rna.tf32.f32 %0, %1;" : "=r"(r) : "f"(x));
    return r;
}
__device__ __forceinline__ float tfr(float x) { return __uint_as_float(f2tf(x)); }

__device__ __forceinline__ void mma8(float d[4], const unsigned a[4], const unsigned b[2]) {
    asm volatile(
        "mma.sync.aligned.m16n8k8.row.col.f32.tf32.tf32.f32 "
        "{%0,%1,%2,%3}, {%4,%5,%6,%7}, {%8,%9}, {%0,%1,%2,%3};\n"
        : "+f"(d[0]), "+f"(d[1]), "+f"(d[2]), "+f"(d[3])
        : "r"(a[0]), "r"(a[1]), "r"(a[2]), "r"(a[3]), "r"(b[0]), "r"(b[1]));
}

__global__ void prep_weights(const float* __restrict__ wqkv, const float* __restrict__ wproj) {
    int i = blockIdx.x * blockDim.x + threadIdx.x;
    if (i < 256 * 768) g_wqkv[i] = tfr(wqkv[i]);
    if (i < 256 * 256) g_wproj[i] = tfr(wproj[i]);
}

__global__ void __launch_bounds__(512, 1)
winattn_kernel(const float* __restrict__ x,
               const float* __restrict__ b_qkv,
               const float* __restrict__ b_proj,
               const float* __restrict__ bias_table,
               float* __restrict__ out)
{
    extern __shared__ float sm[];
    float* sx = sm + SM_X;   // phase1: x; phase2+: attention output (proj A operand)
    float* sq = sm + SM_Q;
    float* sk = sm + SM_K;
    float* sv = sm + SM_V;
    float* sb = sm + SM_B;

    const int tid  = threadIdx.x;
    const int warp = tid >> 5;
    const int lane = tid & 31;
    const int g    = lane >> 2;
    const int tg   = lane & 3;
    const int b    = blockIdx.x;

    // ---- load x[b] (49x256) rounded to tf32; zero v pad rows; stage bias table ----
    const float* xb = x + (size_t)b * NTOK * 256;
    for (int i = tid; i < NTOK * 256 / 4; i += 512) {
        float4 v = ((const float4*)xb)[i];
        int e = i * 4;
        int r = e >> 8, c = e & 255;
        float* d = sx + r * S_STR + c;
        d[0] = tfr(v.x); d[1] = tfr(v.y); d[2] = tfr(v.z); d[3] = tfr(v.w);
    }
    for (int i = tid; i < 7 * S_STR; i += 512) sv[49 * S_STR + i] = 0.f;
    for (int i = tid; i < 169 * 8; i += 512) sb[i] = bias_table[i];
    __syncthreads();

    const int wm = warp >> 3;   // 0..1 : 32-row half
    const int wn = warp & 7;    // 0..7 : 32-col slice within a 256-col chunk
    const float SCALE = 0.17677669529663687f;   // 1/sqrt(32)

    // ================= GEMM1: qkv = x @ w_qkv + b_qkv (q pre-scaled) =================
    {
        const float* p0 = sx + (wm * 32 +  0 + g) * S_STR;
        const float* p1 = sx + (wm * 32 +  8 + g) * S_STR;
        const float* p2 = sx + (wm * 32 + 16 + g) * S_STR;
        const float* p3 = sx + (wm * 32 + 24 + g) * S_STR;

        for (int nc = 0; nc < 3; nc++) {
            const int nb = nc * 256 + wn * 32;
            float acc[2][4][4];
            #pragma unroll
            for (int mt = 0; mt < 2; mt++)
                #pragma unroll
                for (int nt = 0; nt < 4; nt++)
                    #pragma unroll
                    for (int q = 0; q < 4; q++) acc[mt][nt][q] = 0.f;

            unsigned Bb[2][4][2];
            #pragma unroll
            for (int nt = 0; nt < 4; nt++) {
                int n0 = nb + nt * 8 + g;
                Bb[0][nt][0] = __float_as_uint(g_wqkv[tg * 768 + n0]);
                Bb[0][nt][1] = __float_as_uint(g_wqkv[(tg + 4) * 768 + n0]);
            }
            #pragma unroll 4
            for (int ks = 0; ks < 32; ks++) {
                const int k0 = ks * 8;
                const int cur = ks & 1;
                if (ks < 31) {
                    #pragma unroll
                    for (int nt = 0; nt < 4; nt++) {
                        int n0 = nb + nt * 8 + g;
                        Bb[cur ^ 1][nt][0] = __float_as_uint(g_wqkv[(k0 + 8 + tg) * 768 + n0]);
                        Bb[cur ^ 1][nt][1] = __float_as_uint(g_wqkv[(k0 + 12 + tg) * 768 + n0]);
                    }
                }
                unsigned A0[4], A1[4];
                A0[0] = __float_as_uint(p0[k0 + tg]);
                A0[1] = __float_as_uint(p1[k0 + tg]);
                A0[2] = __float_as_uint(p0[k0 + tg + 4]);
                A0[3] = __float_as_uint(p1[k0 + tg + 4]);
                A1[0] = __float_as_uint(p2[k0 + tg]);
                A1[1] = __float_as_uint(p3[k0 + tg]);
                A1[2] = __float_as_uint(p2[k0 + tg + 4]);
                A1[3] = __float_as_uint(p3[k0 + tg + 4]);
                #pragma unroll
                for (int nt = 0; nt < 4; nt++) {
                    mma8(acc[0][nt], A0, Bb[cur][nt]);
                    mma8(acc[1][nt], A1, Bb[cur][nt]);
                }
            }
            // epilogue
            float* dst = (nc == 0) ? sq : (nc == 1) ? sk : sv;
            const float sc = (nc == 0) ? SCALE : 1.0f;
            #pragma unroll
            for (int mt = 0; mt < 2; mt++) {
                int r = wm * 32 + mt * 16 + g;
                #pragma unroll
                for (int nt = 0; nt < 4; nt++) {
                    int cc = wn * 32 + nt * 8 + 2 * tg;
                    float bq0 = __ldg(&b_qkv[nc * 256 + cc]);
                    float bq1 = __ldg(&b_qkv[nc * 256 + cc + 1]);
                    if (r < NTOK) {
                        float2 v;
                        v.x = tfr((acc[mt][nt][0] + bq0) * sc);
                        v.y = tfr((acc[mt][nt][1] + bq1) * sc);
                        *(float2*)(dst + r * S_STR + cc) = v;
                    }
                    if (r + 8 < NTOK) {
                        float2 v;
                        v.x = tfr((acc[mt][nt][2] + bq0) * sc);
                        v.y = tfr((acc[mt][nt][3] + bq1) * sc);
                        *(float2*)(dst + (r + 8) * S_STR + cc) = v;
                    }
                }
            }
        }
    }
    __syncthreads();

    // ================= Attention: head = warp>>1, two warps split the M range =================
    {
        const int h = warp >> 1;
        float* sout = sx;

        for (int mi = 0; mi < 2; mi++) {
            const int m0 = (warp & 1) * 32 + mi * 16;
            float S[7][4];
            #pragma unroll
            for (int jt = 0; jt < 7; jt++)
                #pragma unroll
                for (int q = 0; q < 4; q++) S[jt][q] = 0.f;

            // S = q @ k^T  (scale pre-folded into q)
            #pragma unroll
            for (int kt = 0; kt < 4; kt++) {
                int c0 = h * 32 + kt * 8 + tg;
                unsigned A[4];
                A[0] = __float_as_uint(sq[(m0 + g)     * S_STR + c0]);
                A[1] = __float_as_uint(sq[(m0 + 8 + g) * S_STR + c0]);
                A[2] = __float_as_uint(sq[(m0 + g)     * S_STR + c0 + 4]);
                A[3] = __float_as_uint(sq[(m0 + 8 + g) * S_STR + c0 + 4]);
                #pragma unroll
                for (int jt = 0; jt < 7; jt++) {
                    int tok = jt * 8 + g;
                    unsigned Bf[2];
                    Bf[0] = __float_as_uint(sk[tok * S_STR + c0]);
                    Bf[1] = __float_as_uint(sk[tok * S_STR + c0 + 4]);
                    mma8(S[jt], A, Bf);
                }
            }

            // + relative-position bias (smem) + column mask
            int r0 = m0 + g, r1 = m0 + 8 + g;
            int r0c = (r0 < NTOK) ? r0 : 0;
            int r1c = (r1 < NTOK) ? r1 : 0;
            int hi0 = r0c / 7, wi0 = r0c % 7;
            int hi1 = r1c / 7, wi1 = r1c % 7;
            #pragma unroll
            for (int jt = 0; jt < 7; jt++) {
                #pragma unroll
                for (int e = 0; e < 2; e++) {
                    int j = jt * 8 + 2 * tg + e;
                    if (j < NTOK) {
                        int hj = j / 7, wj = j % 7;
                        S[jt][e]     += sb[((hi0 - hj + 6) * 13 + (wi0 - wj + 6)) * 8 + h];
                        S[jt][2 + e] += sb[((hi1 - hj + 6) * 13 + (wi1 - wj + 6)) * 8 + h];
                    } else {
                        S[jt][e]     = -1e30f;
                        S[jt][2 + e] = -1e30f;
                    }
                }
            }

            // softmax over quads
            float mx0 = -1e30f, mx1 = -1e30f;
            #pragma unroll
            for (int jt = 0; jt < 7; jt++) {
                mx0 = fmaxf(mx0, fmaxf(S[jt][0], S[jt][1]));
                mx1 = fmaxf(mx1, fmaxf(S[jt][2], S[jt][3]));
            }
            mx0 = fmaxf(mx0, __shfl_xor_sync(FULL, mx0, 1));
            mx0 = fmaxf(mx0, __shfl_xor_sync(FULL, mx0, 2));
            mx1 = fmaxf(mx1, __shfl_xor_sync(FULL, mx1, 1));
            mx1 = fmaxf(mx1, __shfl_xor_sync(FULL, mx1, 2));
            float s0 = 0.f, s1 = 0.f;
            #pragma unroll
            for (int jt = 0; jt < 7; jt++) {
                S[jt][0] = __expf(S[jt][0] - mx0); s0 += S[jt][0];
                S[jt][1] = __expf(S[jt][1] - mx0); s0 += S[jt][1];
                S[jt][2] = __expf(S[jt][2] - mx1); s1 += S[jt][2];
                S[jt][3] = __expf(S[jt][3] - mx1); s1 += S[jt][3];
            }
            s0 += __shfl_xor_sync(FULL, s0, 1); s0 += __shfl_xor_sync(FULL, s0, 2);
            s1 += __shfl_xor_sync(FULL, s1, 1); s1 += __shfl_xor_sync(FULL, s1, 2);
            float i0 = 1.f / s0, i1 = 1.f / s1;

            unsigned Pt[7][4];
            #pragma unroll
            for (int jt = 0; jt < 7; jt++) {
                Pt[jt][0] = f2tf(S[jt][0] * i0);
                Pt[jt][1] = f2tf(S[jt][1] * i0);
                Pt[jt][2] = f2tf(S[jt][2] * i1);
                Pt[jt][3] = f2tf(S[jt][3] * i1);
            }

            // O = P @ v  (C-frag -> A-frag via intra-quad shfl)
            float O[4][4];
            #pragma unroll
            for (int nt = 0; nt < 4; nt++)
                #pragma unroll
                for (int q = 0; q < 4; q++) O[nt][q] = 0.f;

            const int  src = g * 4 + (tg >> 1);
            const bool odd = (tg & 1);
            #pragma unroll
            for (int kt = 0; kt < 7; kt++) {
                unsigned q0 = __shfl_sync(FULL, Pt[kt][0], src);
                unsigned q1 = __shfl_sync(FULL, Pt[kt][1], src);
                unsigned q2 = __shfl_sync(FULL, Pt[kt][2], src);
                unsigned q3 = __shfl_sync(FULL, Pt[kt][3], src);
                unsigned q4 = __shfl_sync(FULL, Pt[kt][0], src + 2);
                unsigned q5 = __shfl_sync(FULL, Pt[kt][1], src + 2);
                unsigned q6 = __shfl_sync(FULL, Pt[kt][2], src + 2);
                unsigned q7 = __shfl_sync(FULL, Pt[kt][3], src + 2);
                unsigned A[4];
                A[0] = odd ? q1 : q0;
                A[1] = odd ? q3 : q2;
                A[2] = odd ? q5 : q4;
                A[3] = odd ? q7 : q6;
                int t0 = kt * 8 + tg;
                #pragma unroll
                for (int nt = 0; nt < 4; nt++) {
                    int col = h * 32 + nt * 8 + g;
                    unsigned Bf[2];
                    Bf[0] = __float_as_uint(sv[t0       * S_STR + col]);
                    Bf[1] = __float_as_uint(sv[(t0 + 4) * S_STR + col]);
                    mma8(O[nt], A, Bf);
                }
            }
            #pragma unroll
            for (int nt = 0; nt < 4; nt++) {
                int c = h * 32 + nt * 8 + 2 * tg;
                if (r0 < NTOK) {
                    float2 v; v.x = tfr(O[nt][0]); v.y = tfr(O[nt][1]);
                    *(float2*)(sout + r0 * S_STR + c) = v;
                }
                if (r1 < NTOK) {
                    float2 v; v.x = tfr(O[nt][2]); v.y = tfr(O[nt][3]);
                    *(float2*)(sout + r1 * S_STR + c) = v;
                }
            }
        }
    }
    __syncthreads();

    // ================= Proj: out = attn_out @ w_proj + b_proj =================
    {
        const float* p0 = sx + (wm * 32 +  0 + g) * S_STR;
        const float* p1 = sx + (wm * 32 +  8 + g) * S_STR;
        const float* p2 = sx + (wm * 32 + 16 + g) * S_STR;
        const float* p3 = sx + (wm * 32 + 24 + g) * S_STR;
        const int nb = wn * 32;

        float acc[2][4][4];
        #pragma unroll
        for (int mt = 0; mt < 2; mt++)
            #pragma unroll
            for (int nt = 0; nt < 4; nt++)
                #pragma unroll
                for (int q = 0; q < 4; q++) acc[mt][nt][q] = 0.f;

        unsigned Bb[2][4][2];
        #pragma unroll
        for (int nt = 0; nt < 4; nt++) {
            int n0 = nb + nt * 8 + g;
            Bb[0][nt][0] = __float_as_uint(g_wproj[tg * 256 + n0]);
            Bb[0][nt][1] = __float_as_uint(g_wproj[(tg + 4) * 256 + n0]);
        }
        #pragma unroll 4
        for (int ks = 0; ks < 32; ks++) {
            const int k0 = ks * 8;
            const int cur = ks & 1;
            if (ks < 31) {
                #pragma unroll
                for (int nt = 0; nt < 4; nt++) {
                    int n0 = nb + nt * 8 + g;
                    Bb[cur ^ 1][nt][0] = __float_as_uint(g_wproj[(k0 + 8 + tg) * 256 + n0]);
                    Bb[cur ^ 1][nt][1] = __float_as_uint(g_wproj[(k0 + 12 + tg) * 256 + n0]);
                }
            }
            unsigned A0[4], A1[4];
            A0[0] = __float_as_uint(p0[k0 + tg]);
            A0[1] = __float_as_uint(p1[k0 + tg]);
            A0[2] = __float_as_uint(p0[k0 + tg + 4]);
            A0[3] = __float_as_uint(p1[k0 + tg + 4]);
            A1[0] = __float_as_uint(p2[k0 + tg]);
            A1[1] = __float_as_uint(p3[k0 + tg]);
            A1[2] = __float_as_uint(p2[k0 + tg + 4]);
            A1[3] = __float_as_uint(p3[k0 + tg + 4]);
            #pragma unroll
            for (int nt = 0; nt < 4; nt++) {
                mma8(acc[0][nt], A0, Bb[cur][nt]);
                mma8(acc[1][nt], A1, Bb[cur][nt]);
            }
        }
        #pragma unroll
        for (int mt = 0; mt < 2; mt++) {
            int r = wm * 32 + mt * 16 + g;
            #pragma unroll
            for (int nt = 0; nt < 4; nt++) {
                int c = nb + nt * 8 + 2 * tg;
                float bp0 = __ldg(&b_proj[c]), bp1 = __ldg(&b_proj[c + 1]);
                if (r < NTOK) {
                    float2 v; v.x = acc[mt][nt][0] + bp0; v.y = acc[mt][nt][1] + bp1;
                    *(float2*)(out + ((size_t)b * NTOK + r) * 256 + c) = v;
                }
                if (r + 8 < NTOK) {
                    float2 v; v.x = acc[mt][nt][2] + bp0; v.y = acc[mt][nt][3] + bp1;
                    *(float2*)(out + ((size_t)b * NTOK + r + 8) * 256 + c) = v;
                }
            }
        }
    }
}

extern "C" void kernel_launch(void* const* d_in, const int* in_sizes, int n_in,
                              void* d_out, int out_size)
{
    const float* x          = (const float*)d_in[0];
    const float* w_qkv      = (const float*)d_in[1];
    const float* b_qkv      = (const float*)d_in[2];
    const float* w_proj     = (const float*)d_in[3];
    const float* b_proj     = (const float*)d_in[4];
    const float* bias_table = (const float*)d_in[5];

    const int B = in_sizes[0] / (NTOK * 256);

    cudaFuncSetAttribute(winattn_kernel,
                         cudaFuncAttributeMaxDynamicSharedMemorySize,
                         SMEM_FLOATS * (int)sizeof(float));

    prep_weights<<<768, 256>>>(w_qkv, w_proj);
    winattn_kernel<<<B, 512, SMEM_FLOATS * sizeof(float)>>>(
        x, b_qkv, b_proj, bias_table, (float*)d_out);
}

// round 4
// speedup vs baseline: 1.1056x; 1.0030x over previous
#include <cuda_runtime.h>
#include <cstdint>

#define FULL 0xFFFFFFFFu

static constexpr int NTOK = 49;      // tokens per window
static constexpr int S_STR = 260;    // smem row stride; 260 % 32 == 4 -> conflict-free fragments
// region layout (floats). Over-reads of "padded" A rows 49..63 intentionally spill into the
// next region; those mma output rows are discarded by store predicates.
static constexpr int SM_X = 0;                    // 49 rows: x tile, later attention output
static constexpr int SM_Q = 49 * S_STR;           // 49 rows
static constexpr int SM_K = SM_Q + 49 * S_STR;    // 56 rows (rows 49..55 read by B-frags, masked)
static constexpr int SM_V = SM_K + 56 * S_STR;    // 56 rows (rows 49..55 MUST be zero: 0*Inf=NaN)
static constexpr int SM_B = SM_V + 56 * S_STR;    // bias table 169*8 floats
static constexpr int SMEM_FLOATS = SM_B + 169 * 8;   // 55952 floats = 223808 B

// tf32-rounded weights (rounded once per launch, reused by all CTAs)
__device__ float g_wqkv[256 * 768];
__device__ float g_wproj[256 * 256];

__device__ __forceinline__ unsigned f2tf(float x) {
    unsigned r;
    asm("cvt.rna.tf32.f32 %0, %1;" : "=r"(r) : "f"(x));
    return r;
}
__device__ __forceinline__ float tfr(float x) { return __uint_as_float(f2tf(x)); }

__device__ __forceinline__ void mma8(float d[4], const unsigned a[4], const unsigned b[2]) {
    asm volatile(
        "mma.sync.aligned.m16n8k8.row.col.f32.tf32.tf32.f32 "
        "{%0,%1,%2,%3}, {%4,%5,%6,%7}, {%8,%9}, {%0,%1,%2,%3};\n"
        : "+f"(d[0]), "+f"(d[1]), "+f"(d[2]), "+f"(d[3])
        : "r"(a[0]), "r"(a[1]), "r"(a[2]), "r"(a[3]), "r"(b[0]), "r"(b[1]));
}

__global__ void prep_weights(const float* __restrict__ wqkv, const float* __restrict__ wproj) {
    int i = blockIdx.x * blockDim.x + threadIdx.x;
    if (i < 256 * 768) g_wqkv[i] = tfr(wqkv[i]);
    if (i < 256 * 256) g_wproj[i] = tfr(wproj[i]);
}

__global__ void __launch_bounds__(512, 1)
winattn_kernel(const float* __restrict__ x,
               const float* __restrict__ b_qkv,
               const float* __restrict__ b_proj,
               const float* __restrict__ bias_table,
               float* __restrict__ out)
{
    extern __shared__ float sm[];
    float* sx = sm + SM_X;   // phase1: x; phase2+: attention output (proj A operand)
    float* sq = sm + SM_Q;
    float* sk = sm + SM_K;
    float* sv = sm + SM_V;
    float* sb = sm + SM_B;

    const int tid  = threadIdx.x;
    const int warp = tid >> 5;
    const int lane = tid & 31;
    const int g    = lane >> 2;
    const int tg   = lane & 3;
    const int b    = blockIdx.x;

    // ---- load x[b] (49x256) rounded to tf32; zero v pad rows; stage bias table ----
    const float* xb = x + (size_t)b * NTOK * 256;
    for (int i = tid; i < NTOK * 256 / 4; i += 512) {
        float4 v = ((const float4*)xb)[i];
        int e = i * 4;
        int r = e >> 8, c = e & 255;
        float* d = sx + r * S_STR + c;
        d[0] = tfr(v.x); d[1] = tfr(v.y); d[2] = tfr(v.z); d[3] = tfr(v.w);
    }
    for (int i = tid; i < 7 * S_STR; i += 512) sv[49 * S_STR + i] = 0.f;
    for (int i = tid; i < 169 * 8; i += 512) sb[i] = bias_table[i];
    __syncthreads();

    const int wm = warp >> 3;   // 0..1 : 32-row half
    const int wn = warp & 7;    // 0..7 : 32-col slice within a 256-col chunk
    const float SCALE = 0.17677669529663687f;   // 1/sqrt(32)

    // ================= GEMM1: qkv = x @ w_qkv + b_qkv (q pre-scaled) =================
    {
        const float* p0 = sx + (wm * 32 +  0 + g) * S_STR;
        const float* p1 = sx + (wm * 32 +  8 + g) * S_STR;
        const float* p2 = sx + (wm * 32 + 16 + g) * S_STR;
        const float* p3 = sx + (wm * 32 + 24 + g) * S_STR;

        for (int nc = 0; nc < 3; nc++) {
            const int nb = nc * 256 + wn * 32;
            float acc[2][4][4];
            #pragma unroll
            for (int mt = 0; mt < 2; mt++)
                #pragma unroll
                for (int nt = 0; nt < 4; nt++)
                    #pragma unroll
                    for (int q = 0; q < 4; q++) acc[mt][nt][q] = 0.f;

            unsigned Bb[2][4][2];
            #pragma unroll
            for (int nt = 0; nt < 4; nt++) {
                int n0 = nb + nt * 8 + g;
                Bb[0][nt][0] = __float_as_uint(g_wqkv[tg * 768 + n0]);
                Bb[0][nt][1] = __float_as_uint(g_wqkv[(tg + 4) * 768 + n0]);
            }
            #pragma unroll 4
            for (int ks = 0; ks < 32; ks++) {
                const int k0 = ks * 8;
                const int cur = ks & 1;
                if (ks < 31) {
                    #pragma unroll
                    for (int nt = 0; nt < 4; nt++) {
                        int n0 = nb + nt * 8 + g;
                        Bb[cur ^ 1][nt][0] = __float_as_uint(g_wqkv[(k0 + 8 + tg) * 768 + n0]);
                        Bb[cur ^ 1][nt][1] = __float_as_uint(g_wqkv[(k0 + 12 + tg) * 768 + n0]);
                    }
                }
                unsigned A0[4], A1[4];
                A0[0] = __float_as_uint(p0[k0 + tg]);
                A0[1] = __float_as_uint(p1[k0 + tg]);
                A0[2] = __float_as_uint(p0[k0 + tg + 4]);
                A0[3] = __float_as_uint(p1[k0 + tg + 4]);
                A1[0] = __float_as_uint(p2[k0 + tg]);
                A1[1] = __float_as_uint(p3[k0 + tg]);
                A1[2] = __float_as_uint(p2[k0 + tg + 4]);
                A1[3] = __float_as_uint(p3[k0 + tg + 4]);
                #pragma unroll
                for (int nt = 0; nt < 4; nt++) {
                    mma8(acc[0][nt], A0, Bb[cur][nt]);
                    mma8(acc[1][nt], A1, Bb[cur][nt]);
                }
            }
            // epilogue
            float* dst = (nc == 0) ? sq : (nc == 1) ? sk : sv;
            const float sc = (nc == 0) ? SCALE : 1.0f;
            #pragma unroll
            for (int mt = 0; mt < 2; mt++) {
                int r = wm * 32 + mt * 16 + g;
                #pragma unroll
                for (int nt = 0; nt < 4; nt++) {
                    int cc = wn * 32 + nt * 8 + 2 * tg;
                    float bq0 = __ldg(&b_qkv[nc * 256 + cc]);
                    float bq1 = __ldg(&b_qkv[nc * 256 + cc + 1]);
                    if (r < NTOK) {
                        float2 v;
                        v.x = tfr((acc[mt][nt][0] + bq0) * sc);
                        v.y = tfr((acc[mt][nt][1] + bq1) * sc);
                        *(float2*)(dst + r * S_STR + cc) = v;
                    }
                    if (r + 8 < NTOK) {
                        float2 v;
                        v.x = tfr((acc[mt][nt][2] + bq0) * sc);
                        v.y = tfr((acc[mt][nt][3] + bq1) * sc);
                        *(float2*)(dst + (r + 8) * S_STR + cc) = v;
                    }
                }
            }
        }
    }
    __syncthreads();

    // ================= Attention: head = warp>>1, two warps split the M range =================
    {
        const int h = warp >> 1;
        float* sout = sx;

        for (int mi = 0; mi < 2; mi++) {
            const int m0 = (warp & 1) * 32 + mi * 16;
            float S[7][4];
            #pragma unroll
            for (int jt = 0; jt < 7; jt++)
                #pragma unroll
                for (int q = 0; q < 4; q++) S[jt][q] = 0.f;

            // S = q @ k^T  (scale pre-folded into q)
            #pragma unroll
            for (int kt = 0; kt < 4; kt++) {
                int c0 = h * 32 + kt * 8 + tg;
                unsigned A[4];
                A[0] = __float_as_uint(sq[(m0 + g)     * S_STR + c0]);
                A[1] = __float_as_uint(sq[(m0 + 8 + g) * S_STR + c0]);
                A[2] = __float_as_uint(sq[(m0 + g)     * S_STR + c0 + 4]);
                A[3] = __float_as_uint(sq[(m0 + 8 + g) * S_STR + c0 + 4]);
                #pragma unroll
                for (int jt = 0; jt < 7; jt++) {
                    int tok = jt * 8 + g;
                    unsigned Bf[2];
                    Bf[0] = __float_as_uint(sk[tok * S_STR + c0]);
                    Bf[1] = __float_as_uint(sk[tok * S_STR + c0 + 4]);
                    mma8(S[jt], A, Bf);
                }
            }

            // + relative-position bias (smem) + column mask
            int r0 = m0 + g, r1 = m0 + 8 + g;
            int r0c = (r0 < NTOK) ? r0 : 0;
            int r1c = (r1 < NTOK) ? r1 : 0;
            int hi0 = r0c / 7, wi0 = r0c % 7;
            int hi1 = r1c / 7, wi1 = r1c % 7;
            #pragma unroll
            for (int jt = 0; jt < 7; jt++) {
                #pragma unroll
                for (int e = 0; e < 2; e++) {
                    int j = jt * 8 + 2 * tg + e;
                    if (j < NTOK) {
                        int hj = j / 7, wj = j % 7;
                        S[jt][e]     += sb[((hi0 - hj + 6) * 13 + (wi0 - wj + 6)) * 8 + h];
                        S[jt][2 + e] += sb[((hi1 - hj + 6) * 13 + (wi1 - wj + 6)) * 8 + h];
                    } else {
                        S[jt][e]     = -1e30f;
                        S[jt][2 + e] = -1e30f;
                    }
                }
            }

            // softmax over quads
            float mx0 = -1e30f, mx1 = -1e30f;
            #pragma unroll
            for (int jt = 0; jt < 7; jt++) {
                mx0 = fmaxf(mx0, fmaxf(S[jt][0], S[jt][1]));
                mx1 = fmaxf(mx1, fmaxf(S[jt][2], S[jt][3]));
            }
            mx0 = fmaxf(mx0, __shfl_xor_sync(FULL, mx0, 1));
            mx0 = fmaxf(mx0, __shfl_xor_sync(FULL, mx0, 2));
            mx1 = fmaxf(mx1, __shfl_xor_sync(FULL, mx1, 1));
            mx1 = fmaxf(mx1, __shfl_xor_sync(FULL, mx1, 2));
            float s0 = 0.f, s1 = 0.f;
            #pragma unroll
            for (int jt = 0; jt < 7; jt++) {
                S[jt][0] = __expf(S[jt][0] - mx0); s0 += S[jt][0];
                S[jt][1] = __expf(S[jt][1] - mx0); s0 += S[jt][1];
                S[jt][2] = __expf(S[jt][2] - mx1); s1 += S[jt][2];
                S[jt][3] = __expf(S[jt][3] - mx1); s1 += S[jt][3];
            }
            s0 += __shfl_xor_sync(FULL, s0, 1); s0 += __shfl_xor_sync(FULL, s0, 2);
            s1 += __shfl_xor_sync(FULL, s1, 1); s1 += __shfl_xor_sync(FULL, s1, 2);
            float i0 = 1.f / s0, i1 = 1.f / s1;

            unsigned Pt[7][4];
            #pragma unroll
            for (int jt = 0; jt < 7; jt++) {
                Pt[jt][0] = f2tf(S[jt][0] * i0);
                Pt[jt][1] = f2tf(S[jt][1] * i0);
                Pt[jt][2] = f2tf(S[jt][2] * i1);
                Pt[jt][3] = f2tf(S[jt][3] * i1);
            }

            // O = P @ v  (C-frag -> A-frag via intra-quad shfl)
            float O[4][4];
            #pragma unroll
            for (int nt = 0; nt < 4; nt++)
                #pragma unroll
                for (int q = 0; q < 4; q++) O[nt][q] = 0.f;

            const int  src = g * 4 + (tg >> 1);
            const bool odd = (tg & 1);
            #pragma unroll
            for (int kt = 0; kt < 7; kt++) {
                unsigned q0 = __shfl_sync(FULL, Pt[kt][0], src);
                unsigned q1 = __shfl_sync(FULL, Pt[kt][1], src);
                unsigned q2 = __shfl_sync(FULL, Pt[kt][2], src);
                unsigned q3 = __shfl_sync(FULL, Pt[kt][3], src);
                unsigned q4 = __shfl_sync(FULL, Pt[kt][0], src + 2);
                unsigned q5 = __shfl_sync(FULL, Pt[kt][1], src + 2);
                unsigned q6 = __shfl_sync(FULL, Pt[kt][2], src + 2);
                unsigned q7 = __shfl_sync(FULL, Pt[kt][3], src + 2);
                unsigned A[4];
                A[0] = odd ? q1 : q0;
                A[1] = odd ? q3 : q2;
                A[2] = odd ? q5 : q4;
                A[3] = odd ? q7 : q6;
                int t0 = kt * 8 + tg;
                #pragma unroll
                for (int nt = 0; nt < 4; nt++) {
                    int col = h * 32 + nt * 8 + g;
                    unsigned Bf[2];
                    Bf[0] = __float_as_uint(sv[t0       * S_STR + col]);
                    Bf[1] = __float_as_uint(sv[(t0 + 4) * S_STR + col]);
                    mma8(O[nt], A, Bf);
                }
            }
            #pragma unroll
            for (int nt = 0; nt < 4; nt++) {
                int c = h * 32 + nt * 8 + 2 * tg;
                if (r0 < NTOK) {
                    float2 v; v.x = tfr(O[nt][0]); v.y = tfr(O[nt][1]);
                    *(float2*)(sout + r0 * S_STR + c) = v;
                }
                if (r1 < NTOK) {
                    float2 v; v.x = tfr(O[nt][2]); v.y = tfr(O[nt][3]);
                    *(float2*)(sout + r1 * S_STR + c) = v;
                }
            }
        }
    }
    __syncthreads();

    // ================= Proj: out = attn_out @ w_proj + b_proj =================
    {
        const float* p0 = sx + (wm * 32 +  0 + g) * S_STR;
        const float* p1 = sx + (wm * 32 +  8 + g) * S_STR;
        const float* p2 = sx + (wm * 32 + 16 + g) * S_STR;
        const float* p3 = sx + (wm * 32 + 24 + g) * S_STR;
        const int nb = wn * 32;

        float acc[2][4][4];
        #pragma unroll
        for (int mt = 0; mt < 2; mt++)
            #pragma unroll
            for (int nt = 0; nt < 4; nt++)
                #pragma unroll
                for (int q = 0; q < 4; q++) acc[mt][nt][q] = 0.f;

        unsigned Bb[2][4][2];
        #pragma unroll
        for (int nt = 0; nt < 4; nt++) {
            int n0 = nb + nt * 8 + g;
            Bb[0][nt][0] = __float_as_uint(g_wproj[tg * 256 + n0]);
            Bb[0][nt][1] = __float_as_uint(g_wproj[(tg + 4) * 256 + n0]);
        }
        #pragma unroll 4
        for (int ks = 0; ks < 32; ks++) {
            const int k0 = ks * 8;
            const int cur = ks & 1;
            if (ks < 31) {
                #pragma unroll
                for (int nt = 0; nt < 4; nt++) {
                    int n0 = nb + nt * 8 + g;
                    Bb[cur ^ 1][nt][0] = __float_as_uint(g_wproj[(k0 + 8 + tg) * 256 + n0]);
                    Bb[cur ^ 1][nt][1] = __float_as_uint(g_wproj[(k0 + 12 + tg) * 256 + n0]);
                }
            }
            unsigned A0[4], A1[4];
            A0[0] = __float_as_uint(p0[k0 + tg]);
            A0[1] = __float_as_uint(p1[k0 + tg]);
            A0[2] = __float_as_uint(p0[k0 + tg + 4]);
            A0[3] = __float_as_uint(p1[k0 + tg + 4]);
            A1[0] = __float_as_uint(p2[k0 + tg]);
            A1[1] = __float_as_uint(p3[k0 + tg]);
            A1[2] = __float_as_uint(p2[k0 + tg + 4]);
            A1[3] = __float_as_uint(p3[k0 + tg + 4]);
            #pragma unroll
            for (int nt = 0; nt < 4; nt++) {
                mma8(acc[0][nt], A0, Bb[cur][nt]);
                mma8(acc[1][nt], A1, Bb[cur][nt]);
            }
        }
        #pragma unroll
        for (int mt = 0; mt < 2; mt++) {
            int r = wm * 32 + mt * 16 + g;
            #pragma unroll
            for (int nt = 0; nt < 4; nt++) {
                int c = nb + nt * 8 + 2 * tg;
                float bp0 = __ldg(&b_proj[c]), bp1 = __ldg(&b_proj[c + 1]);
                if (r < NTOK) {
                    float2 v; v.x = acc[mt][nt][0] + bp0; v.y = acc[mt][nt][1] + bp1;
                    *(float2*)(out + ((size_t)b * NTOK + r) * 256 + c) = v;
                }
                if (r + 8 < NTOK) {
                    float2 v; v.x = acc[mt][nt][2] + bp0; v.y = acc[mt][nt][3] + bp1;
                    *(float2*)(out + ((size_t)b * NTOK + r + 8) * 256 + c) = v;
                }
            }
        }
    }
}

extern "C" void kernel_launch(void* const* d_in, const int* in_sizes, int n_in,
                              void* d_out, int out_size)
{
    const float* x          = (const float*)d_in[0];
    const float* w_qkv      = (const float*)d_in[1];
    const float* b_qkv      = (const float*)d_in[2];
    const float* w_proj     = (const float*)d_in[3];
    const float* b_proj     = (const float*)d_in[4];
    const float* bias_table = (const float*)d_in[5];

    const int B = in_sizes[0] / (NTOK * 256);

    cudaFuncSetAttribute(winattn_kernel,
                         cudaFuncAttributeMaxDynamicSharedMemorySize,
                         SMEM_FLOATS * (int)sizeof(float));

    prep_weights<<<768, 256>>>(w_qkv, w_proj);
    winattn_kernel<<<B, 512, SMEM_FLOATS * sizeof(float)>>>(
        x, b_qkv, b_proj, bias_table, (float*)d_out);
}

// round 5
// speedup vs baseline: 1.2909x; 1.1677x over previous
#include <cuda_runtime.h>
#include <cuda_fp16.h>
#include <cstdint>

#define FULL 0xFFFFFFFFu
static constexpr int NTOK = 49, S2 = 264, R = 64;
static constexpr int HX = 0, HQ = R * S2, HK = 2 * R * S2, HV = 3 * R * S2, HB = 4 * R * S2;
static constexpr int SMEM_BYTES = 8 * R * S2 + 169 * 8 * 4;   // 135168 + 5408

__device__ unsigned g_wq[768 * 128];   // half2-packed W_qkv: [n][k/2]
__device__ unsigned g_wp[256 * 128];   // half2-packed W_proj

__device__ __forceinline__ unsigned pack2(float a, float b) {
    __half2 h = __floats2half2_rn(a, b); return *(unsigned*)&h;
}
__device__ __forceinline__ uint32_t smem_u32(const void* p) {
    uint32_t a;
    asm("{ .reg .u64 t; cvta.to.shared.u64 t, %1; cvt.u32.u64 %0, t; }" : "=r"(a) : "l"(p));
    return a;
}
__device__ __forceinline__ void mma16(float d[4], unsigned a0, unsigned a1, unsigned a2, unsigned a3,
                                      unsigned b0, unsigned b1) {
    asm volatile("mma.sync.aligned.m16n8k16.row.col.f32.f16.f16.f32 "
                 "{%0,%1,%2,%3},{%4,%5,%6,%7},{%8,%9},{%0,%1,%2,%3};\n"
                 : "+f"(d[0]), "+f"(d[1]), "+f"(d[2]), "+f"(d[3])
                 : "r"(a0), "r"(a1), "r"(a2), "r"(a3), "r"(b0), "r"(b1));
}
__device__ __forceinline__ void ldsm4(unsigned r[4], uint32_t a) {
    asm volatile("ldmatrix.sync.aligned.m8n8.x4.shared.b16 {%0,%1,%2,%3}, [%4];"
                 : "=r"(r[0]), "=r"(r[1]), "=r"(r[2]), "=r"(r[3]) : "r"(a));
}
__device__ __forceinline__ void ldsm4t(unsigned r[4], uint32_t a) {
    asm volatile("ldmatrix.sync.aligned.m8n8.x4.trans.shared.b16 {%0,%1,%2,%3}, [%4];"
                 : "=r"(r[0]), "=r"(r[1]), "=r"(r[2]), "=r"(r[3]) : "r"(a));
}

__global__ void prep(const float* __restrict__ wq, const float* __restrict__ wp) {
    int i = blockIdx.x * blockDim.x + threadIdx.x;
    if (i < 768 * 128) { int n = i >> 7, k = (i & 127) * 2; g_wq[i] = pack2(wq[k * 768 + n], wq[(k + 1) * 768 + n]); }
    if (i < 256 * 128) { int n = i >> 7, k = (i & 127) * 2; g_wp[i] = pack2(wp[k * 256 + n], wp[(k + 1) * 256 + n]); }
}

__global__ void __launch_bounds__(512, 1)
wink(const float* __restrict__ x, const float* __restrict__ bqkv, const float* __restrict__ bproj,
     const float* __restrict__ btab, float* __restrict__ out)
{
    extern __shared__ __half sh[];
    float* sb = (float*)(sh + HB);
    const uint32_t smb = smem_u32(sh);
    const int tid = threadIdx.x, warp = tid >> 5, lane = tid & 31, g = lane >> 2, tg = lane & 3;
    const int b = blockIdx.x;

    // ---- x -> half smem; zero sk/sv pad rows; stage bias table ----
    const float* xb = x + (size_t)b * NTOK * 256;
    for (int i = tid; i < NTOK * 64; i += 512) {
        float4 v = ((const float4*)xb)[i];
        int r = i >> 6, c = (i & 63) * 4;
        unsigned* d = (unsigned*)(sh + HX + r * S2 + c);
        d[0] = pack2(v.x, v.y); d[1] = pack2(v.z, v.w);
    }
    for (int i = tid; i < 15 * S2; i += 512) {
        sh[HK + 49 * S2 + i] = __float2half(0.f);
        sh[HV + 49 * S2 + i] = __float2half(0.f);
    }
    for (int i = tid; i < 169 * 8; i += 512) sb[i] = btab[i];
    __syncthreads();

    const int wm = warp >> 3, wn = warp & 7;
    // ldmatrix lane-offset patterns (in halves)
    const int aoff  = ((lane & 7) + ((lane >> 3) & 1) * 8) * S2 + (lane >> 4) * 8;       // A (x4)
    const int boffS = ((lane >> 4) * 8 + (lane & 7)) * S2 + ((lane >> 3) & 1) * 8;       // K (x4)
    const int voff  = (lane & 15) * S2 + (lane >> 4) * 8;                                // V (x4 trans)

    // ================= GEMM1: qkv = x @ Wqkv + b (q pre-scaled) =================
    {
        uint32_t aA0 = smb + 2 * (HX + (wm * 32) * S2 + aoff);
        uint32_t aA1 = aA0 + 2 * 16 * S2;
        for (int nc = 0; nc < 3; nc++) {
            float acc[2][4][4] = {};
            const unsigned* W = g_wq + (nc * 256 + wn * 32) * 128;
            unsigned Bb[2][4][2];
            #pragma unroll
            for (int nt = 0; nt < 4; nt++) {
                int n0 = nt * 8 + g;
                Bb[0][nt][0] = W[n0 * 128 + tg]; Bb[0][nt][1] = W[n0 * 128 + tg + 4];
            }
            #pragma unroll 4
            for (int ks = 0; ks < 16; ks++) {
                int cur = ks & 1;
                if (ks < 15) {
                    #pragma unroll
                    for (int nt = 0; nt < 4; nt++) {
                        int n0 = nt * 8 + g;
                        Bb[cur ^ 1][nt][0] = W[n0 * 128 + (ks + 1) * 8 + tg];
                        Bb[cur ^ 1][nt][1] = W[n0 * 128 + (ks + 1) * 8 + tg + 4];
                    }
                }
                unsigned A0[4], A1[4];
                ldsm4(A0, aA0 + 2 * ks * 16);
                ldsm4(A1, aA1 + 2 * ks * 16);
                #pragma unroll
                for (int nt = 0; nt < 4; nt++) {
                    mma16(acc[0][nt], A0[0], A0[1], A0[2], A0[3], Bb[cur][nt][0], Bb[cur][nt][1]);
                    mma16(acc[1][nt], A1[0], A1[1], A1[2], A1[3], Bb[cur][nt][0], Bb[cur][nt][1]);
                }
            }
            __half* dst = sh + ((nc == 0) ? HQ : (nc == 1) ? HK : HV);
            float sc = (nc == 0) ? 0.17677669529663687f : 1.f;
            #pragma unroll
            for (int mt = 0; mt < 2; mt++) {
                int r = wm * 32 + mt * 16 + g;
                #pragma unroll
                for (int nt = 0; nt < 4; nt++) {
                    int cc = wn * 32 + nt * 8 + 2 * tg;
                    float b0 = bqkv[nc * 256 + cc], b1 = bqkv[nc * 256 + cc + 1];
                    if (r < NTOK)
                        *(unsigned*)(dst + r * S2 + cc) = pack2((acc[mt][nt][0] + b0) * sc, (acc[mt][nt][1] + b1) * sc);
                    if (r + 8 < NTOK)
                        *(unsigned*)(dst + (r + 8) * S2 + cc) = pack2((acc[mt][nt][2] + b0) * sc, (acc[mt][nt][3] + b1) * sc);
                }
            }
        }
    }
    __syncthreads();

    // ================= Attention: head = warp>>1; C-frag == A-frag, no shuffles =================
    {
        const int h = warp >> 1;
        for (int mi = 0; mi < 2; mi++) {
            int m0 = (warp & 1) * 32 + mi * 16;
            float S[8][4] = {};
            uint32_t aQ = smb + 2 * (HQ + m0 * S2 + aoff + h * 32);
            #pragma unroll
            for (int kt = 0; kt < 2; kt++) {
                unsigned A[4]; ldsm4(A, aQ + 2 * kt * 16);
                #pragma unroll
                for (int jp = 0; jp < 4; jp++) {
                    unsigned Bk[4];
                    ldsm4(Bk, smb + 2 * (HK + jp * 16 * S2 + boffS + h * 32 + kt * 16));
                    mma16(S[2 * jp],     A[0], A[1], A[2], A[3], Bk[0], Bk[1]);
                    mma16(S[2 * jp + 1], A[0], A[1], A[2], A[3], Bk[2], Bk[3]);
                }
            }
            int r0 = m0 + g, r1 = m0 + 8 + g;
            int r0c = (r0 < NTOK) ? r0 : 0, r1c = (r1 < NTOK) ? r1 : 0;
            int hi0 = r0c / 7, wi0 = r0c % 7, hi1 = r1c / 7, wi1 = r1c % 7;
            #pragma unroll
            for (int jt = 0; jt < 8; jt++) {
                #pragma unroll
                for (int e = 0; e < 2; e++) {
                    int j = jt * 8 + 2 * tg + e;
                    if (j < NTOK) {
                        int hj = j / 7, wj = j % 7;
                        S[jt][e]     += sb[((hi0 - hj + 6) * 13 + (wi0 - wj + 6)) * 8 + h];
                        S[jt][2 + e] += sb[((hi1 - hj + 6) * 13 + (wi1 - wj + 6)) * 8 + h];
                    } else { S[jt][e] = -1e30f; S[jt][2 + e] = -1e30f; }
                }
            }
            float mx0 = -1e30f, mx1 = -1e30f;
            #pragma unroll
            for (int jt = 0; jt < 8; jt++) {
                mx0 = fmaxf(mx0, fmaxf(S[jt][0], S[jt][1]));
                mx1 = fmaxf(mx1, fmaxf(S[jt][2], S[jt][3]));
            }
            mx0 = fmaxf(mx0, __shfl_xor_sync(FULL, mx0, 1)); mx0 = fmaxf(mx0, __shfl_xor_sync(FULL, mx0, 2));
            mx1 = fmaxf(mx1, __shfl_xor_sync(FULL, mx1, 1)); mx1 = fmaxf(mx1, __shfl_xor_sync(FULL, mx1, 2));
            float s0 = 0.f, s1 = 0.f;
            #pragma unroll
            for (int jt = 0; jt < 8; jt++) {
                S[jt][0] = __expf(S[jt][0] - mx0); s0 += S[jt][0];
                S[jt][1] = __expf(S[jt][1] - mx0); s0 += S[jt][1];
                S[jt][2] = __expf(S[jt][2] - mx1); s1 += S[jt][2];
                S[jt][3] = __expf(S[jt][3] - mx1); s1 += S[jt][3];
            }
            s0 += __shfl_xor_sync(FULL, s0, 1); s0 += __shfl_xor_sync(FULL, s0, 2);
            s1 += __shfl_xor_sync(FULL, s1, 1); s1 += __shfl_xor_sync(FULL, s1, 2);
            float i0 = 1.f / s0, i1 = 1.f / s1;
            unsigned PA[8][2];
            #pragma unroll
            for (int jt = 0; jt < 8; jt++) {
                PA[jt][0] = pack2(S[jt][0] * i0, S[jt][1] * i0);
                PA[jt][1] = pack2(S[jt][2] * i1, S[jt][3] * i1);
            }
            float O[4][4] = {};
            #pragma unroll
            for (int kt = 0; kt < 4; kt++) {
                #pragma unroll
                for (int np = 0; np < 2; np++) {
                    unsigned Bv[4];
                    ldsm4t(Bv, smb + 2 * (HV + kt * 16 * S2 + voff + h * 32 + np * 16));
                    mma16(O[2 * np],     PA[2 * kt][0], PA[2 * kt][1], PA[2 * kt + 1][0], PA[2 * kt + 1][1], Bv[0], Bv[1]);
                    mma16(O[2 * np + 1], PA[2 * kt][0], PA[2 * kt][1], PA[2 * kt + 1][0], PA[2 * kt + 1][1], Bv[2], Bv[3]);
                }
            }
            #pragma unroll
            for (int nt = 0; nt < 4; nt++) {
                int c = h * 32 + nt * 8 + 2 * tg;
                if (r0 < NTOK) *(unsigned*)(sh + HX + r0 * S2 + c) = pack2(O[nt][0], O[nt][1]);
                if (r1 < NTOK) *(unsigned*)(sh + HX + r1 * S2 + c) = pack2(O[nt][2], O[nt][3]);
            }
        }
    }
    __syncthreads();

    // ================= Proj: out = attn_out @ Wproj + b =================
    {
        uint32_t aA0 = smb + 2 * (HX + (wm * 32) * S2 + aoff);
        uint32_t aA1 = aA0 + 2 * 16 * S2;
        float acc[2][4][4] = {};
        const unsigned* W = g_wp + (wn * 32) * 128;
        unsigned Bb[2][4][2];
        #pragma unroll
        for (int nt = 0; nt < 4; nt++) {
            int n0 = nt * 8 + g;
            Bb[0][nt][0] = W[n0 * 128 + tg]; Bb[0][nt][1] = W[n0 * 128 + tg + 4];
        }
        #pragma unroll 4
        for (int ks = 0; ks < 16; ks++) {
            int cur = ks & 1;
            if (ks < 15) {
                #pragma unroll
                for (int nt = 0; nt < 4; nt++) {
                    int n0 = nt * 8 + g;
                    Bb[cur ^ 1][nt][0] = W[n0 * 128 + (ks + 1) * 8 + tg];
                    Bb[cur ^ 1][nt][1] = W[n0 * 128 + (ks + 1) * 8 + tg + 4];
                }
            }
            unsigned A0[4], A1[4];
            ldsm4(A0, aA0 + 2 * ks * 16);
            ldsm4(A1, aA1 + 2 * ks * 16);
            #pragma unroll
            for (int nt = 0; nt < 4; nt++) {
                mma16(acc[0][nt], A0[0], A0[1], A0[2], A0[3], Bb[cur][nt][0], Bb[cur][nt][1]);
                mma16(acc[1][nt], A1[0], A1[1], A1[2], A1[3], Bb[cur][nt][0], Bb[cur][nt][1]);
            }
        }
        #pragma unroll
        for (int mt = 0; mt < 2; mt++) {
            int r = wm * 32 + mt * 16 + g;
            #pragma unroll
            for (int nt = 0; nt < 4; nt++) {
                int c = wn * 32 + nt * 8 + 2 * tg;
                float b0 = bproj[c], b1 = bproj[c + 1];
                if (r < NTOK) {
                    float2 v; v.x = acc[mt][nt][0] + b0; v.y = acc[mt][nt][1] + b1;
                    *(float2*)(out + ((size_t)b * NTOK + r) * 256 + c) = v;
                }
                if (r + 8 < NTOK) {
                    float2 v; v.x = acc[mt][nt][2] + b0; v.y = acc[mt][nt][3] + b1;
                    *(float2*)(out + ((size_t)b * NTOK + r + 8) * 256 + c) = v;
                }
            }
        }
    }
}

extern "C" void kernel_launch(void* const* d_in, const int* in_sizes, int n_in,
                              void* d_out, int out_size)
{
    const float* x     = (const float*)d_in[0];
    const float* wqkv  = (const float*)d_in[1];
    const float* bq    = (const float*)d_in[2];
    const float* wproj = (const float*)d_in[3];
    const float* bp    = (const float*)d_in[4];
    const float* btab  = (const float*)d_in[5];
    const int B = in_sizes[0] / (NTOK * 256);

    cudaFuncSetAttribute(wink, cudaFuncAttributeMaxDynamicSharedMemorySize, SMEM_BYTES);
    prep<<<384, 256>>>(wqkv, wproj);
    wink<<<B, 512, SMEM_BYTES>>>(x, bq, bp, btab, (float*)d_out);
}

// round 6
// speedup vs baseline: 2.8795x; 2.2306x over previous
#include <cuda_runtime.h>
#include <cuda_fp16.h>
#include <cstdint>

#define FULL 0xFFFFFFFFu
static constexpr int NTOK = 49, S2 = 264, R = 64;
static constexpr int HX = 0, HQ = R * S2, HK = 2 * R * S2, HV = 3 * R * S2, HB = 4 * R * S2;
static constexpr int SMEM_BYTES = 8 * R * S2 + 169 * 8 * 4;

// fragment-order packed weights: per (chunk, wn, ks): uint4[2][32]
__device__ uint4 g_wq4[24576];   // 3 chunks * 8 wn * 16 ks * 2 * 32
__device__ uint4 g_wp4[8192];    // 1 chunk * 8 wn * 16 ks * 2 * 32

__device__ __forceinline__ unsigned pack2(float a, float b) {
    __half2 h = __floats2half2_rn(a, b); return *(unsigned*)&h;
}
__device__ __forceinline__ uint32_t smem_u32(const void* p) {
    uint32_t a;
    asm("{ .reg .u64 t; cvta.to.shared.u64 t, %1; cvt.u32.u64 %0, t; }" : "=r"(a) : "l"(p));
    return a;
}
__device__ __forceinline__ void mma16(float d[4], unsigned a0, unsigned a1, unsigned a2, unsigned a3,
                                      unsigned b0, unsigned b1) {
    asm volatile("mma.sync.aligned.m16n8k16.row.col.f32.f16.f16.f32 "
                 "{%0,%1,%2,%3},{%4,%5,%6,%7},{%8,%9},{%0,%1,%2,%3};\n"
                 : "+f"(d[0]), "+f"(d[1]), "+f"(d[2]), "+f"(d[3])
                 : "r"(a0), "r"(a1), "r"(a2), "r"(a3), "r"(b0), "r"(b1));
}
__device__ __forceinline__ void ldsm4(unsigned r[4], uint32_t a) {
    asm volatile("ldmatrix.sync.aligned.m8n8.x4.shared.b16 {%0,%1,%2,%3}, [%4];"
                 : "=r"(r[0]), "=r"(r[1]), "=r"(r[2]), "=r"(r[3]) : "r"(a));
}
__device__ __forceinline__ void ldsm4t(unsigned r[4], uint32_t a) {
    asm volatile("ldmatrix.sync.aligned.m8n8.x4.trans.shared.b16 {%0,%1,%2,%3}, [%4];"
                 : "=r"(r[0]), "=r"(r[1]), "=r"(r[2]), "=r"(r[3]) : "r"(a));
}

// pack one uint4 of fragment-order weights
__device__ __forceinline__ uint4 fragpack(const float* w, int ldn, int col_a, int k0) {
    uint4 v;
    v.x = pack2(w[k0 * ldn + col_a],       w[(k0 + 1) * ldn + col_a]);
    v.y = pack2(w[(k0 + 8) * ldn + col_a], w[(k0 + 9) * ldn + col_a]);
    v.z = pack2(w[k0 * ldn + col_a + 8],       w[(k0 + 1) * ldn + col_a + 8]);
    v.w = pack2(w[(k0 + 8) * ldn + col_a + 8], w[(k0 + 9) * ldn + col_a + 8]);
    return v;
}

__global__ void prep(const float* __restrict__ wq, const float* __restrict__ wp) {
    int idx = blockIdx.x * blockDim.x + threadIdx.x;   // 32768 threads
    int lane = idx & 31, p = (idx >> 5) & 1, ks = (idx >> 6) & 15, wn = (idx >> 10) & 7;
    int n_a = wn * 32 + p * 16 + (lane >> 2);
    int k0  = ks * 16 + 2 * (lane & 3);
    if (idx < 24576) {
        int nc = idx >> 13;
        g_wq4[idx] = fragpack(wq, 768, nc * 256 + n_a, k0);
    }
    if (idx < 8192) {
        g_wp4[idx] = fragpack(wp, 256, n_a, k0);
    }
}

__global__ void __launch_bounds__(512, 1)
wink(const float* __restrict__ x, const float* __restrict__ bqkv, const float* __restrict__ bproj,
     const float* __restrict__ btab, float* __restrict__ out)
{
    extern __shared__ __half sh[];
    float* sb = (float*)(sh + HB);
    const uint32_t smb = smem_u32(sh);
    const int tid = threadIdx.x, warp = tid >> 5, lane = tid & 31, g = lane >> 2, tg = lane & 3;
    const int b = blockIdx.x;

    const float* xb = x + (size_t)b * NTOK * 256;
    for (int i = tid; i < NTOK * 64; i += 512) {
        float4 v = ((const float4*)xb)[i];
        int r = i >> 6, c = (i & 63) * 4;
        unsigned* d = (unsigned*)(sh + HX + r * S2 + c);
        d[0] = pack2(v.x, v.y); d[1] = pack2(v.z, v.w);
    }
    for (int i = tid; i < 15 * S2; i += 512) {
        sh[HK + 49 * S2 + i] = __float2half(0.f);
        sh[HV + 49 * S2 + i] = __float2half(0.f);
    }
    for (int i = tid; i < 169 * 8; i += 512) sb[i] = btab[i];
    __syncthreads();

    const int wm = warp >> 3, wn = warp & 7;
    const int aoff  = ((lane & 7) + ((lane >> 3) & 1) * 8) * S2 + (lane >> 4) * 8;
    const int boffS = ((lane >> 4) * 8 + (lane & 7)) * S2 + ((lane >> 3) & 1) * 8;
    const int voff  = (lane & 15) * S2 + (lane >> 4) * 8;

    // ================= GEMM1: qkv = x @ Wqkv + b (q pre-scaled) =================
    {
        uint32_t aA0 = smb + 2 * (HX + (wm * 32) * S2 + aoff);
        uint32_t aA1 = aA0 + 2 * 16 * S2;
        for (int nc = 0; nc < 3; nc++) {
            float acc[2][4][4] = {};
            const uint4* W = g_wq4 + (nc * 8 + wn) * 1024 + lane;
            uint4 Bb[2][2];
            Bb[0][0] = W[0]; Bb[0][1] = W[32];
            #pragma unroll 4
            for (int ks = 0; ks < 16; ks++) {
                int cur = ks & 1;
                if (ks < 15) {
                    Bb[cur ^ 1][0] = W[(ks + 1) * 64];
                    Bb[cur ^ 1][1] = W[(ks + 1) * 64 + 32];
                }
                unsigned A0[4], A1[4];
                ldsm4(A0, aA0 + 2 * ks * 16);
                ldsm4(A1, aA1 + 2 * ks * 16);
                mma16(acc[0][0], A0[0], A0[1], A0[2], A0[3], Bb[cur][0].x, Bb[cur][0].y);
                mma16(acc[0][1], A0[0], A0[1], A0[2], A0[3], Bb[cur][0].z, Bb[cur][0].w);
                mma16(acc[0][2], A0[0], A0[1], A0[2], A0[3], Bb[cur][1].x, Bb[cur][1].y);
                mma16(acc[0][3], A0[0], A0[1], A0[2], A0[3], Bb[cur][1].z, Bb[cur][1].w);
                mma16(acc[1][0], A1[0], A1[1], A1[2], A1[3], Bb[cur][0].x, Bb[cur][0].y);
                mma16(acc[1][1], A1[0], A1[1], A1[2], A1[3], Bb[cur][0].z, Bb[cur][0].w);
                mma16(acc[1][2], A1[0], A1[1], A1[2], A1[3], Bb[cur][1].x, Bb[cur][1].y);
                mma16(acc[1][3], A1[0], A1[1], A1[2], A1[3], Bb[cur][1].z, Bb[cur][1].w);
            }
            __half* dst = sh + ((nc == 0) ? HQ : (nc == 1) ? HK : HV);
            float sc = (nc == 0) ? 0.17677669529663687f : 1.f;
            #pragma unroll
            for (int mt = 0; mt < 2; mt++) {
                int r = wm * 32 + mt * 16 + g;
                #pragma unroll
                for (int nt = 0; nt < 4; nt++) {
                    // fragment n-order: nt 0,1 -> p=0 (cols +0,+8); nt 2,3 -> p=1 (cols +16,+24)
                    int cc = wn * 32 + (nt >> 1) * 16 + (nt & 1) * 8 + 2 * tg;
                    float b0 = bqkv[nc * 256 + cc], b1 = bqkv[nc * 256 + cc + 1];
                    if (r < NTOK)
                        *(unsigned*)(dst + r * S2 + cc) = pack2((acc[mt][nt][0] + b0) * sc, (acc[mt][nt][1] + b1) * sc);
                    if (r + 8 < NTOK)
                        *(unsigned*)(dst + (r + 8) * S2 + cc) = pack2((acc[mt][nt][2] + b0) * sc, (acc[mt][nt][3] + b1) * sc);
                }
            }
        }
    }
    __syncthreads();

    // ================= Attention: head = warp>>1 =================
    {
        const int h = warp >> 1;
        for (int mi = 0; mi < 2; mi++) {
            int m0 = (warp & 1) * 32 + mi * 16;
            float S[8][4] = {};
            uint32_t aQ = smb + 2 * (HQ + m0 * S2 + aoff + h * 32);
            #pragma unroll
            for (int kt = 0; kt < 2; kt++) {
                unsigned A[4]; ldsm4(A, aQ + 2 * kt * 16);
                #pragma unroll
                for (int jp = 0; jp < 4; jp++) {
                    unsigned Bk[4];
                    ldsm4(Bk, smb + 2 * (HK + jp * 16 * S2 + boffS + h * 32 + kt * 16));
                    mma16(S[2 * jp],     A[0], A[1], A[2], A[3], Bk[0], Bk[1]);
                    mma16(S[2 * jp + 1], A[0], A[1], A[2], A[3], Bk[2], Bk[3]);
                }
            }
            int r0 = m0 + g, r1 = m0 + 8 + g;
            int r0c = (r0 < NTOK) ? r0 : 0, r1c = (r1 < NTOK) ? r1 : 0;
            int hi0 = r0c / 7, wi0 = r0c % 7, hi1 = r1c / 7, wi1 = r1c % 7;
            #pragma unroll
            for (int jt = 0; jt < 8; jt++) {
                #pragma unroll
                for (int e = 0; e < 2; e++) {
                    int j = jt * 8 + 2 * tg + e;
                    if (j < NTOK) {
                        int hj = j / 7, wj = j % 7;
                        S[jt][e]     += sb[((hi0 - hj + 6) * 13 + (wi0 - wj + 6)) * 8 + h];
                        S[jt][2 + e] += sb[((hi1 - hj + 6) * 13 + (wi1 - wj + 6)) * 8 + h];
                    } else { S[jt][e] = -1e30f; S[jt][2 + e] = -1e30f; }
                }
            }
            float mx0 = -1e30f, mx1 = -1e30f;
            #pragma unroll
            for (int jt = 0; jt < 8; jt++) {
                mx0 = fmaxf(mx0, fmaxf(S[jt][0], S[jt][1]));
                mx1 = fmaxf(mx1, fmaxf(S[jt][2], S[jt][3]));
            }
            mx0 = fmaxf(mx0, __shfl_xor_sync(FULL, mx0, 1)); mx0 = fmaxf(mx0, __shfl_xor_sync(FULL, mx0, 2));
            mx1 = fmaxf(mx1, __shfl_xor_sync(FULL, mx1, 1)); mx1 = fmaxf(mx1, __shfl_xor_sync(FULL, mx1, 2));
            float s0 = 0.f, s1 = 0.f;
            #pragma unroll
            for (int jt = 0; jt < 8; jt++) {
                S[jt][0] = __expf(S[jt][0] - mx0); s0 += S[jt][0];
                S[jt][1] = __expf(S[jt][1] - mx0); s0 += S[jt][1];
                S[jt][2] = __expf(S[jt][2] - mx1); s1 += S[jt][2];
                S[jt][3] = __expf(S[jt][3] - mx1); s1 += S[jt][3];
            }
            s0 += __shfl_xor_sync(FULL, s0, 1); s0 += __shfl_xor_sync(FULL, s0, 2);
            s1 += __shfl_xor_sync(FULL, s1, 1); s1 += __shfl_xor_sync(FULL, s1, 2);
            float i0 = 1.f / s0, i1 = 1.f / s1;
            unsigned PA[8][2];
            #pragma unroll
            for (int jt = 0; jt < 8; jt++) {
                PA[jt][0] = pack2(S[jt][0] * i0, S[jt][1] * i0);
                PA[jt][1] = pack2(S[jt][2] * i1, S[jt][3] * i1);
            }
            float O[4][4] = {};
            #pragma unroll
            for (int kt = 0; kt < 4; kt++) {
                #pragma unroll
                for (int np = 0; np < 2; np++) {
                    unsigned Bv[4];
                    ldsm4t(Bv, smb + 2 * (HV + kt * 16 * S2 + voff + h * 32 + np * 16));
                    mma16(O[2 * np],     PA[2 * kt][0], PA[2 * kt][1], PA[2 * kt + 1][0], PA[2 * kt + 1][1], Bv[0], Bv[1]);
                    mma16(O[2 * np + 1], PA[2 * kt][0], PA[2 * kt][1], PA[2 * kt + 1][0], PA[2 * kt + 1][1], Bv[2], Bv[3]);
                }
            }
            #pragma unroll
            for (int nt = 0; nt < 4; nt++) {
                int c = h * 32 + nt * 8 + 2 * tg;
                if (r0 < NTOK) *(unsigned*)(sh + HX + r0 * S2 + c) = pack2(O[nt][0], O[nt][1]);
                if (r1 < NTOK) *(unsigned*)(sh + HX + r1 * S2 + c) = pack2(O[nt][2], O[nt][3]);
            }
        }
    }
    __syncthreads();

    // ================= Proj: out = attn_out @ Wproj + b =================
    {
        uint32_t aA0 = smb + 2 * (HX + (wm * 32) * S2 + aoff);
        uint32_t aA1 = aA0 + 2 * 16 * S2;
        float acc[2][4][4] = {};
        const uint4* W = g_wp4 + wn * 1024 + lane;
        uint4 Bb[2][2];
        Bb[0][0] = W[0]; Bb[0][1] = W[32];
        #pragma unroll 4
        for (int ks = 0; ks < 16; ks++) {
            int cur = ks & 1;
            if (ks < 15) {
                Bb[cur ^ 1][0] = W[(ks + 1) * 64];
                Bb[cur ^ 1][1] = W[(ks + 1) * 64 + 32];
            }
            unsigned A0[4], A1[4];
            ldsm4(A0, aA0 + 2 * ks * 16);
            ldsm4(A1, aA1 + 2 * ks * 16);
            mma16(acc[0][0], A0[0], A0[1], A0[2], A0[3], Bb[cur][0].x, Bb[cur][0].y);
            mma16(acc[0][1], A0[0], A0[1], A0[2], A0[3], Bb[cur][0].z, Bb[cur][0].w);
            mma16(acc[0][2], A0[0], A0[1], A0[2], A0[3], Bb[cur][1].x, Bb[cur][1].y);
            mma16(acc[0][3], A0[0], A0[1], A0[2], A0[3], Bb[cur][1].z, Bb[cur][1].w);
            mma16(acc[1][0], A1[0], A1[1], A1[2], A1[3], Bb[cur][0].x, Bb[cur][0].y);
            mma16(acc[1][1], A1[0], A1[1], A1[2], A1[3], Bb[cur][0].z, Bb[cur][0].w);
            mma16(acc[1][2], A1[0], A1[1], A1[2], A1[3], Bb[cur][1].x, Bb[cur][1].y);
            mma16(acc[1][3], A1[0], A1[1], A1[2], A1[3], Bb[cur][1].z, Bb[cur][1].w);
        }
        #pragma unroll
        for (int mt = 0; mt < 2; mt++) {
            int r = wm * 32 + mt * 16 + g;
            #pragma unroll
            for (int nt = 0; nt < 4; nt++) {
                int c = wn * 32 + (nt >> 1) * 16 + (nt & 1) * 8 + 2 * tg;
                float b0 = bproj[c], b1 = bproj[c + 1];
                if (r < NTOK) {
                    float2 v; v.x = acc[mt][nt][0] + b0; v.y = acc[mt][nt][1] + b1;
                    *(float2*)(out + ((size_t)b * NTOK + r) * 256 + c) = v;
                }
                if (r + 8 < NTOK) {
                    float2 v; v.x = acc[mt][nt][2] + b0; v.y = acc[mt][nt][3] + b1;
                    *(float2*)(out + ((size_t)b * NTOK + r + 8) * 256 + c) = v;
                }
            }
        }
    }
}

extern "C" void kernel_launch(void* const* d_in, const int* in_sizes, int n_in,
                              void* d_out, int out_size)
{
    const float* x     = (const float*)d_in[0];
    const float* wqkv  = (const float*)d_in[1];
    const float* bq    = (const float*)d_in[2];
    const float* wproj = (const float*)d_in[3];
    const float* bp    = (const float*)d_in[4];
    const float* btab  = (const float*)d_in[5];
    const int B = in_sizes[0] / (NTOK * 256);

    cudaFuncSetAttribute(wink, cudaFuncAttributeMaxDynamicSharedMemorySize, SMEM_BYTES);
    prep<<<128, 256>>>(wqkv, wproj);
    wink<<<B, 512, SMEM_BYTES>>>(x, bq, bp, btab, (float*)d_out);
}